// round 1
// baseline (speedup 1.0000x reference)
#include <cuda_runtime.h>
#include <math.h>

#define NQ 14
#define BATCH 2048
#define TOTAL (BATCH * NQ)

struct MaskArgs {
    unsigned m[NQ];   // m_w = P(e_w)  (index-bit mask)
    unsigned r[NQ];   // parity mask: bit_w(P^-1 j) = parity(j & r_w)
    int      k[NQ];   // popcount(m_w & r_w) mod 4
};

__global__ void qulinear_kernel(const float* __restrict__ x,
                                const float* __restrict__ u3,
                                float* __restrict__ out,
                                MaskArgs M)
{
    int t = blockIdx.x * blockDim.x + threadIdx.x;
    if (t >= TOTAL) return;
    int b = t / NQ;
    int w = t - b * NQ;

    // Per-qubit single-qubit expectation values of the pre-CNOT product state.
    // ry = atan(x), rz = atan(x^2):
    //   <Z> = -sin(ry)            = -x / sqrt(1+x^2)
    //   <X> =  cos(rz) cos(ry)   = 1 / (sqrt(1+x^4) sqrt(1+x^2))
    //   Y   =  sin(rz) cos(ry)   = x^2 / (sqrt(1+x^4) sqrt(1+x^2))
    float Zq[NQ], Xq[NQ], Yq[NQ];
#pragma unroll
    for (int v = 0; v < NQ; v++) {
        float xv  = x[b * NQ + v];
        float x2  = xv * xv;
        float c1  = rsqrtf(1.0f + x2);        // cos(ry)
        float c2  = rsqrtf(1.0f + x2 * x2);   // cos(rz)
        Zq[v] = -xv * c1;
        Xq[v] = c2 * c1;
        Yq[v] = x2 * c2 * c1;
    }

    unsigned mw = M.m[w];
    unsigned rw = M.r[w];

    // D = P0 - P1 = prod over r-bits of <Z>
    // A = prod over m-bits of <X>                       (unsigned coherence sum)
    // B = prod with signs: m&r -> Y (carries i), m&~r -> X, ~m&r -> Z
    float D = 1.0f, A = 1.0f, B = 1.0f;
#pragma unroll
    for (int v = 0; v < NQ; v++) {
        int p = (NQ - 1) - v;                 // qubit v lives at index bit p
        bool mb = (mw >> p) & 1u;
        bool rb = (rw >> p) & 1u;
        if (rb) D *= Zq[v];
        if (mb) A *= Xq[v];
        float f = mb ? (rb ? Yq[v] : Xq[v]) : (rb ? Zq[v] : 1.0f);
        B *= f;
    }

    // O = U3^dag Z U3 : O00 = cos(th), O01 = -e^{i lam} sin(th)  (phi cancels)
    float th  = u3[w * 3 + 0];
    float lam = u3[w * 3 + 2];
    float snt, ct;
    sincosf(th, &snt, &ct);
    float cl, sl;
    sincosf(lam, &sl, &cl);

    // <Z_w> = ct*D + Re(O01)*A + Re(O01 * i^k)*B
    float coefA = -snt * cl;
    float re_ik;                              // Re(i^k e^{i lam})
    switch (M.k[w] & 3) {
        case 0:  re_ik =  cl; break;
        case 1:  re_ik = -sl; break;
        case 2:  re_ik = -cl; break;
        default: re_ik =  sl; break;
    }
    float coefB = -snt * re_ik;

    out[t] = ct * D + coefA * A + coefB * B;
}

static void compute_masks(MaskArgs& M)
{
    // CNOT list: for step in (1,2): for c in 0..13: t = (c+step)%14
    int cs[28], ts[28];
    int n = 0;
    for (int step = 1; step <= 2; step++)
        for (int c = 0; c < NQ; c++) { cs[n] = c; ts[n] = (c + step) % NQ; n++; }

    // state' = state[perm] repeatedly  =>  final[i] = init[P(i)], P = p1∘p2∘...∘p28
    auto applyP = [&](unsigned i) {           // evaluate p1(p2(...p28(i)))
        for (int q = 27; q >= 0; q--) {
            unsigned cm = 1u << (NQ - 1 - cs[q]);
            unsigned tm = 1u << (NQ - 1 - ts[q]);
            if (i & cm) i ^= tm;
        }
        return i;
    };
    auto applyPinv = [&](unsigned j) {        // each CNOT is an involution
        for (int q = 0; q < 28; q++) {
            unsigned cm = 1u << (NQ - 1 - cs[q]);
            unsigned tm = 1u << (NQ - 1 - ts[q]);
            if (j & cm) j ^= tm;
        }
        return j;
    };

    for (int w = 0; w < NQ; w++)
        M.m[w] = applyP(1u << (NQ - 1 - w));

    for (int w = 0; w < NQ; w++) {
        unsigned r = 0;
        for (int v = 0; v < NQ; v++) {
            unsigned img = applyPinv(1u << (NQ - 1 - v));
            if ((img >> (NQ - 1 - w)) & 1u) r |= 1u << (NQ - 1 - v);
        }
        M.r[w] = r;
    }

    for (int w = 0; w < NQ; w++) {
        unsigned o = M.m[w] & M.r[w];
        int k = 0;
        while (o) { k += (int)(o & 1u); o >>= 1; }
        M.k[w] = k & 3;
    }
}

extern "C" void kernel_launch(void* const* d_in, const int* in_sizes, int n_in,
                              void* d_out, int out_size)
{
    // metadata order: x (2048*14), u3_params (14*3). Disambiguate defensively.
    const float* x  = (const float*)d_in[0];
    const float* u3 = (const float*)d_in[1];
    if (n_in >= 2 && in_sizes[0] == NQ * 3) {  // swapped order
        x  = (const float*)d_in[1];
        u3 = (const float*)d_in[0];
    }
    float* out = (float*)d_out;

    MaskArgs M;
    compute_masks(M);

    const int threads = 128;
    const int blocks  = (TOTAL + threads - 1) / threads;
    qulinear_kernel<<<blocks, threads>>>(x, u3, out, M);
}

// round 2
// speedup vs baseline: 1.3264x; 1.3264x over previous
#include <cuda_runtime.h>
#include <math.h>

#define NQ 14
#define BATCH 2048

// ---------------------------------------------------------------------------
// Compile-time GF(2) linear-map masks for the fixed CNOT ladder.
// CNOT list: for step in (1,2): for c in 0..13: t=(c+step)%14  (28 gates).
// Final state: psi[i] = phi[P(i)] with P the composition p1∘p2∘...∘p28.
// ---------------------------------------------------------------------------
__host__ __device__ constexpr unsigned qbit(int q) { return 1u << (NQ - 1 - q); }

__host__ __device__ constexpr unsigned applyP(unsigned i) {
    // evaluate p1(p2(...p28(i))): iterate gate list in reverse
    for (int q = 27; q >= 0; q--) {
        int step = (q < NQ) ? 1 : 2;
        int c = q % NQ;
        int t = (c + step) % NQ;
        if (i & qbit(c)) i ^= qbit(t);
    }
    return i;
}

__host__ __device__ constexpr unsigned applyPinv(unsigned j) {
    for (int q = 0; q < 28; q++) {
        int step = (q < NQ) ? 1 : 2;
        int c = q % NQ;
        int t = (c + step) % NQ;
        if (j & qbit(c)) j ^= qbit(t);
    }
    return j;
}

__host__ __device__ constexpr unsigned maskM(int w) { return applyP(qbit(w)); }

__host__ __device__ constexpr unsigned maskR(int w) {
    unsigned r = 0;
    for (int v = 0; v < NQ; v++)
        if ((applyPinv(qbit(v)) >> (NQ - 1 - w)) & 1u) r |= qbit(v);
    return r;
}

__host__ __device__ constexpr int phaseK(int w) {
    unsigned o = maskM(w) & maskR(w);
    int k = 0;
    while (o) { k += (int)(o & 1u); o >>= 1; }
    return k & 3;
}

// ---------------------------------------------------------------------------
// Per-output body, fully specialized on W: masks are immediate constants, so
// the unrolled loop collapses to straight-line FMULs on only the live factors.
//
// Product-state expectation values (ry = atan(x), rz = atan(x^2)):
//   Z = -x / sqrt(1+x^2)
//   X =  1 / (sqrt(1+x^4) sqrt(1+x^2))
//   Y =  x^2 / (sqrt(1+x^4) sqrt(1+x^2))
// Output_w = cos(th)*D + Re(O01)*A + Re(O01 * i^k)*B,  O01 = -e^{i lam} sin(th)
// ---------------------------------------------------------------------------
template <int W>
__device__ __forceinline__ void body(const float* __restrict__ x,
                                     const float* __restrict__ u3,
                                     float* __restrict__ out)
{
    int b = blockIdx.x * blockDim.x + threadIdx.x;
    if (b >= BATCH) return;

    constexpr unsigned mw = maskM(W);
    constexpr unsigned rw = maskR(W);
    constexpr int      k  = phaseK(W);

    const float* xb = x + b * NQ;

    float th  = __ldg(&u3[3 * W + 0]);
    float lam = __ldg(&u3[3 * W + 2]);
    float snt, ct, sl, cl;
    __sincosf(th,  &snt, &ct);
    __sincosf(lam, &sl,  &cl);

    // split accumulators (even/odd v) to halve the dependent-chain depth
    float D0 = 1.f, D1 = 1.f, A0 = 1.f, A1 = 1.f, B0 = 1.f, B1 = 1.f;

#pragma unroll
    for (int v = 0; v < NQ; v++) {
        const bool mb = (mw >> (NQ - 1 - v)) & 1u;   // constant after unroll
        const bool rb = (rw >> (NQ - 1 - v)) & 1u;
        if (!mb && !rb) continue;                     // dead qubit: no load

        float xv = xb[v];
        float x2 = xv * xv;
        float c1 = rsqrtf(1.0f + x2);        // cos(ry)
        float c2 = rsqrtf(1.0f + x2 * x2);   // cos(rz)

        if (rb) { float Z = -xv * c1;  if (v & 1) D1 *= Z; else D0 *= Z; }
        if (mb) { float X = c2 * c1;   if (v & 1) A1 *= X; else A0 *= X; }
        float f = mb ? (rb ? x2 * c2 * c1 : c2 * c1) : (-xv * c1);
        if (v & 1) B1 *= f; else B0 *= f;
    }

    float D = D0 * D1, A = A0 * A1, B = B0 * B1;

    float coefA = -snt * cl;
    float re_ik = (k == 0) ? cl : (k == 1) ? -sl : (k == 2) ? -cl : sl;  // Re(i^k e^{i lam})
    float coefB = -snt * re_ik;

    out[b * NQ + W] = ct * D + coefA * A + coefB * B;
}

__global__ void __launch_bounds__(256, 1)
qulinear_kernel(const float* __restrict__ x,
                const float* __restrict__ u3,
                float* __restrict__ out)
{
    switch (blockIdx.y) {
        case 0:  body<0>(x, u3, out);  break;
        case 1:  body<1>(x, u3, out);  break;
        case 2:  body<2>(x, u3, out);  break;
        case 3:  body<3>(x, u3, out);  break;
        case 4:  body<4>(x, u3, out);  break;
        case 5:  body<5>(x, u3, out);  break;
        case 6:  body<6>(x, u3, out);  break;
        case 7:  body<7>(x, u3, out);  break;
        case 8:  body<8>(x, u3, out);  break;
        case 9:  body<9>(x, u3, out);  break;
        case 10: body<10>(x, u3, out); break;
        case 11: body<11>(x, u3, out); break;
        case 12: body<12>(x, u3, out); break;
        case 13: body<13>(x, u3, out); break;
    }
}

extern "C" void kernel_launch(void* const* d_in, const int* in_sizes, int n_in,
                              void* d_out, int out_size)
{
    const float* x  = (const float*)d_in[0];
    const float* u3 = (const float*)d_in[1];
    if (n_in >= 2 && in_sizes[0] == NQ * 3) {  // defensive: swapped order
        x  = (const float*)d_in[1];
        u3 = (const float*)d_in[0];
    }
    float* out = (float*)d_out;

    dim3 block(256, 1, 1);
    dim3 grid(BATCH / 256, NQ, 1);   // 8 x 14 = 112 blocks, single wave
    qulinear_kernel<<<grid, block>>>(x, u3, out);
}